// round 5
// baseline (speedup 1.0000x reference)
#include <cuda_runtime.h>
#include <cuda_bf16.h>
#include <math.h>
#include <stdint.h>

#define Bc 2
#define Sc 2048
#define Dc 1024
#define Hc 16
#define DPc 64

static const size_t SZ_QKV  = (size_t)Bc * Sc * Dc;        // 4194304
static const size_t SZ_ATTN = (size_t)Bc * Hc * Sc * Sc;   // 134217728

__device__ float g_ctx[(size_t)Bc * Sc * Dc];
__device__ float g_lbuf[(size_t)Bc * Hc * Sc];

// ---------------------------------------------------------------------------
// helpers
// ---------------------------------------------------------------------------
__device__ __forceinline__ uint32_t smem_u32(const void* p) {
    uint32_t a;
    asm("{ .reg .u64 t; cvta.to.shared.u64 t, %1; cvt.u32.u64 %0, t; }"
        : "=r"(a) : "l"(p));
    return a;
}
__device__ __forceinline__ void mma16816(float* d, const uint32_t* a, const uint32_t* b) {
    asm volatile(
        "mma.sync.aligned.m16n8k16.row.col.f32.bf16.bf16.f32 "
        "{%0,%1,%2,%3}, {%4,%5,%6,%7}, {%8,%9}, {%0,%1,%2,%3};"
        : "+f"(d[0]), "+f"(d[1]), "+f"(d[2]), "+f"(d[3])
        : "r"(a[0]), "r"(a[1]), "r"(a[2]), "r"(a[3]), "r"(b[0]), "r"(b[1]));
}
__device__ __forceinline__ void ldsm4(uint32_t* r, uint32_t addr) {
    asm volatile("ldmatrix.sync.aligned.m8n8.x4.shared.b16 {%0,%1,%2,%3}, [%4];"
                 : "=r"(r[0]), "=r"(r[1]), "=r"(r[2]), "=r"(r[3]) : "r"(addr));
}
__device__ __forceinline__ float fexp2(float x) {
    float r;
    asm("ex2.approx.f32 %0, %1;" : "=f"(r) : "f"(x));
    return r;
}
__device__ __forceinline__ uint32_t pack_hi(float x, float y) {
    __nv_bfloat162 h = __float22bfloat162_rn(make_float2(x, y));
    return *(uint32_t*)&h;
}
__device__ __forceinline__ uint32_t pack_lo(float x, float y) {
    __nv_bfloat16 hx = __float2bfloat16(x), hy = __float2bfloat16(y);
    __nv_bfloat162 l = __float22bfloat162_rn(
        make_float2(x - __bfloat162float(hx), y - __bfloat162float(hy)));
    return *(uint32_t*)&l;
}

// ---------------------------------------------------------------------------
// Tensor-core GEMM body: C = A @ B^T + bias, bf16 hi/lo split (3 mma terms)
// ---------------------------------------------------------------------------
#define ROWB 40
#define PLANE (128 * ROWB * 2)

__device__ __forceinline__
void gemm_body(const float* __restrict__ A, const float* __restrict__ B,
               const float* __restrict__ bias, float* __restrict__ C,
               int M, int N, int K, char* sm)
{
    const uint32_t smb = smem_u32(sm);
    const int tid = threadIdx.x;
    const int wid = tid >> 5, lane = tid & 31;
    const int m0 = blockIdx.y * 128, n0 = blockIdx.x * 128;
    const int warp_m = (wid & 1) * 64;
    const int warp_n = (wid >> 1) * 32;

    auto plane = [&](int buf, int p) -> uint32_t { return (uint32_t)((buf * 4 + p) * PLANE); };

    float acc[4][4][4];
#pragma unroll
    for (int i = 0; i < 4; i++)
#pragma unroll
        for (int j = 0; j < 4; j++)
#pragma unroll
            for (int c = 0; c < 4; c++) acc[i][j][c] = 0.0f;

    const int nch = K / 32;
    float4 ra[4], rb[4];

    auto load_regs = [&](int ch) {
        const size_t gk = (size_t)ch * 32;
#pragma unroll
        for (int e = 0; e < 4; e++) {
            int id = tid + e * 256;
            int row = id >> 3;
            int c4 = (id & 7) << 2;
            ra[e] = *(const float4*)(A + (size_t)(m0 + row) * K + gk + c4);
            rb[e] = *(const float4*)(B + (size_t)(n0 + row) * K + gk + c4);
        }
    };
    auto sts_regs = [&](int buf) {
#pragma unroll
        for (int e = 0; e < 4; e++) {
            int id = tid + e * 256;
            int row = id >> 3;
            int c4 = (id & 7) << 2;
            uint32_t off = (uint32_t)(row * 80 + c4 * 2);
            uint2 h, l;
            h.x = pack_hi(ra[e].x, ra[e].y); h.y = pack_hi(ra[e].z, ra[e].w);
            l.x = pack_lo(ra[e].x, ra[e].y); l.y = pack_lo(ra[e].z, ra[e].w);
            *(uint2*)(sm + plane(buf, 0) + off) = h;
            *(uint2*)(sm + plane(buf, 1) + off) = l;
            h.x = pack_hi(rb[e].x, rb[e].y); h.y = pack_hi(rb[e].z, rb[e].w);
            l.x = pack_lo(rb[e].x, rb[e].y); l.y = pack_lo(rb[e].z, rb[e].w);
            *(uint2*)(sm + plane(buf, 2) + off) = h;
            *(uint2*)(sm + plane(buf, 3) + off) = l;
        }
    };

    load_regs(0);
    sts_regs(0);
    __syncthreads();

    for (int ch = 0; ch < nch; ch++) {
        const int buf = ch & 1;
        if (ch + 1 < nch) load_regs(ch + 1);

        const int arow = lane & 15;
        const int acol = (lane >> 4) * 8;
        const int bg = lane >> 3, bw = lane & 7;

#pragma unroll
        for (int ks = 0; ks < 2; ks++) {
            const int k16 = ks * 16;
            uint32_t ah[4][4], al[4][4];
#pragma unroll
            for (int mt = 0; mt < 4; mt++) {
                uint32_t off = (uint32_t)((warp_m + mt * 16 + arow) * 80 + (k16 + acol) * 2);
                ldsm4(ah[mt], smb + plane(buf, 0) + off);
                ldsm4(al[mt], smb + plane(buf, 1) + off);
            }
            uint32_t bh[4][2], bl[4][2];
#pragma unroll
            for (int nb = 0; nb < 2; nb++) {
                uint32_t off = (uint32_t)((warp_n + nb * 16 + (bg & 1) * 8 + bw) * 80
                                          + (k16 + (bg >> 1) * 8) * 2);
                uint32_t t[4];
                ldsm4(t, smb + plane(buf, 2) + off);
                bh[nb * 2 + 0][0] = t[0]; bh[nb * 2 + 0][1] = t[2];
                bh[nb * 2 + 1][0] = t[1]; bh[nb * 2 + 1][1] = t[3];
                ldsm4(t, smb + plane(buf, 3) + off);
                bl[nb * 2 + 0][0] = t[0]; bl[nb * 2 + 0][1] = t[2];
                bl[nb * 2 + 1][0] = t[1]; bl[nb * 2 + 1][1] = t[3];
            }
#pragma unroll
            for (int mt = 0; mt < 4; mt++)
#pragma unroll
                for (int nt = 0; nt < 4; nt++) {
                    mma16816(acc[mt][nt], ah[mt], bh[nt]);
                    mma16816(acc[mt][nt], ah[mt], bl[nt]);
                    mma16816(acc[mt][nt], al[mt], bh[nt]);
                }
        }

        if (ch + 1 < nch) sts_regs((ch + 1) & 1);
        __syncthreads();
    }

    const int lr = lane >> 2, lc = (lane & 3) * 2;
#pragma unroll
    for (int nt = 0; nt < 4; nt++) {
        int col = n0 + warp_n + nt * 8 + lc;
        float2 bv = *(const float2*)&bias[col];
#pragma unroll
        for (int mt = 0; mt < 4; mt++) {
            int r0 = m0 + warp_m + mt * 16 + lr;
            float2 o0 = make_float2(acc[mt][nt][0] + bv.x, acc[mt][nt][1] + bv.y);
            float2 o1 = make_float2(acc[mt][nt][2] + bv.x, acc[mt][nt][3] + bv.y);
            *(float2*)(C + (size_t)r0 * N + col) = o0;
            *(float2*)(C + (size_t)(r0 + 8) * N + col) = o1;
        }
    }
}

__global__ __launch_bounds__(256, 1)
void gemm_mma_kernel(const float* __restrict__ A, const float* __restrict__ B,
                     const float* __restrict__ bias, float* __restrict__ C,
                     int M, int N, int K)
{
    extern __shared__ __align__(128) char sm[];
    gemm_body(A, B, bias, C, M, N, K, sm);
}

struct QKVParams {
    const float* A[3];
    const float* W[3];
    const float* b[3];
    float*       C[3];
};

__global__ __launch_bounds__(256, 1)
void gemm_mma_qkv(QKVParams p, int M, int N, int K)
{
    extern __shared__ __align__(128) char sm[];
    const int z = blockIdx.z;
    gemm_body(p.A[z], p.W[z], p.b[z], p.C[z], M, N, K, sm);
}

// ---------------------------------------------------------------------------
// Fused single-pass attention. 128x128 S tile per CTA, 8 warps.
// Writes UNNORMALIZED exp(s) to attn (lower-tri tiles), accumulates row sums l
// and unnormalized ctx; scales ctx by 1/l; stores l to g_lbuf.
// ---------------------------------------------------------------------------
#define QROWB 144
#define VROWB 272
#define AQH 0
#define AQL 18432
#define AKH 36864
#define AKL 55296
#define AVH 73728
#define AVL 91136
#define APH 108544
#define APL 143360
#define SM2_TOT 178176

__device__ __forceinline__ void load_tile_hilo(const float* gp, char* sm,
                                               uint32_t offH, uint32_t offL, int tid)
{
#pragma unroll
    for (int e = 0; e < 8; e++) {
        int id = tid + e * 256;
        int row = id >> 4;
        int c = (id & 15) << 2;
        float4 v = *(const float4*)(gp + (size_t)row * Dc + c);
        uint32_t off = (uint32_t)(row * QROWB + c * 2);
        uint2 h, l;
        h.x = pack_hi(v.x, v.y); h.y = pack_hi(v.z, v.w);
        l.x = pack_lo(v.x, v.y); l.y = pack_lo(v.z, v.w);
        *(uint2*)(sm + offH + off) = h;
        *(uint2*)(sm + offL + off) = l;
    }
}

__device__ __forceinline__ void s_tile_mma(float acc[4][4][4], uint32_t smb,
                                           int warp_m, int warp_n, int lane)
{
    const int arow = lane & 15;
    const int acol = (lane >> 4) * 8;
    const int bg = lane >> 3, bw = lane & 7;
#pragma unroll
    for (int ks = 0; ks < 4; ks++) {
        const int k16 = ks * 16;
        uint32_t ah[4][4], al[4][4];
#pragma unroll
        for (int mt = 0; mt < 4; mt++) {
            uint32_t off = (uint32_t)((warp_m + mt * 16 + arow) * QROWB + (k16 + acol) * 2);
            ldsm4(ah[mt], smb + AQH + off);
            ldsm4(al[mt], smb + AQL + off);
        }
        uint32_t bh[4][2], bl[4][2];
#pragma unroll
        for (int nb = 0; nb < 2; nb++) {
            uint32_t off = (uint32_t)((warp_n + nb * 16 + (bg & 1) * 8 + bw) * QROWB
                                      + (k16 + (bg >> 1) * 8) * 2);
            uint32_t t[4];
            ldsm4(t, smb + AKH + off);
            bh[nb * 2 + 0][0] = t[0]; bh[nb * 2 + 0][1] = t[2];
            bh[nb * 2 + 1][0] = t[1]; bh[nb * 2 + 1][1] = t[3];
            ldsm4(t, smb + AKL + off);
            bl[nb * 2 + 0][0] = t[0]; bl[nb * 2 + 0][1] = t[2];
            bl[nb * 2 + 1][0] = t[1]; bl[nb * 2 + 1][1] = t[3];
        }
#pragma unroll
        for (int mt = 0; mt < 4; mt++)
#pragma unroll
            for (int nt = 0; nt < 4; nt++) {
                mma16816(acc[mt][nt], ah[mt], bh[nt]);
                mma16816(acc[mt][nt], ah[mt], bl[nt]);
                mma16816(acc[mt][nt], al[mt], bh[nt]);
            }
    }
}

__global__ __launch_bounds__(256, 1)
void attn_fused_mma(const float* __restrict__ q, const float* __restrict__ k,
                    const float* __restrict__ v, float* __restrict__ attn)
{
    extern __shared__ __align__(128) char sm[];
    const uint32_t smb = smem_u32(sm);
    const int tid = threadIdx.x;
    const int wid = tid >> 5, lane = tid & 31;
    const int b = blockIdx.z, h = blockIdx.y, it = blockIdx.x;
    const int r0 = it * 128;
    const int warp_m = (wid & 1) * 64;
    const int warp_n = (wid >> 1) * 32;
    const int wnp = (wid >> 1) * 16;
    const int lr = lane >> 2, lc2 = (lane & 3) * 2;
    // exp(s/8) = exp2(s * 0.125*log2e)
    const float CE = 0.125f * 1.4426950408889634f;

    const float* qp = q + ((size_t)b * Sc + r0) * Dc + h * DPc;
    const float* kp = k + (size_t)b * Sc * Dc + h * DPc;
    const float* vp = v + (size_t)b * Sc * Dc + h * DPc;
    const size_t bh = (size_t)(b * Hc + h);
    float* attnp = attn + bh * Sc * Sc;

    load_tile_hilo(qp, sm, AQH, AQL, tid);

    float ctx[4][2][4];
#pragma unroll
    for (int i = 0; i < 4; i++)
#pragma unroll
        for (int j = 0; j < 2; j++)
#pragma unroll
            for (int c = 0; c < 4; c++) ctx[i][j][c] = 0.0f;

    float lsum[4][2];
#pragma unroll
    for (int i = 0; i < 4; i++) { lsum[i][0] = 0.0f; lsum[i][1] = 0.0f; }

    const int arow = lane & 15;
    const int acol = (lane >> 4) * 8;
    const int bg = lane >> 3, bw = lane & 7;

    for (int jt = 0; jt <= it; jt++) {
        const int j0 = jt * 128;
        __syncthreads();
        load_tile_hilo(kp + (size_t)j0 * Dc, sm, AKH, AKL, tid);
        // V tile transposed into Vt[d][j] hi/lo
        {
            const int j = tid >> 1;
            const int dbase = (tid & 1) * 32;
            const float* vr = vp + (size_t)(j0 + j) * Dc + dbase;
#pragma unroll
            for (int e = 0; e < 8; e++) {
                float4 vv = *(const float4*)(vr + e * 4);
                float vals[4] = {vv.x, vv.y, vv.z, vv.w};
#pragma unroll
                for (int q4 = 0; q4 < 4; q4++) {
                    int d = dbase + e * 4 + q4;
                    __nv_bfloat16 hb = __float2bfloat16(vals[q4]);
                    __nv_bfloat16 lb = __float2bfloat16(vals[q4] - __bfloat162float(hb));
                    *(__nv_bfloat16*)(sm + AVH + d * VROWB + j * 2) = hb;
                    *(__nv_bfloat16*)(sm + AVL + d * VROWB + j * 2) = lb;
                }
            }
        }
        __syncthreads();

        float acc[4][4][4];
#pragma unroll
        for (int i = 0; i < 4; i++)
#pragma unroll
            for (int j = 0; j < 4; j++)
#pragma unroll
                for (int c = 0; c < 4; c++) acc[i][j][c] = 0.0f;

        s_tile_mma(acc, smb, warp_m, warp_n, lane);

        const bool diag = (jt == it);
#pragma unroll
        for (int mt = 0; mt < 4; mt++)
#pragma unroll
            for (int hf = 0; hf < 2; hf++) {
                const int rowg = warp_m + mt * 16 + lr + hf * 8;
                const int growg = r0 + rowg;
                float rl = 0.0f;
#pragma unroll
                for (int nt = 0; nt < 4; nt++) {
                    int col = warp_n + nt * 8 + lc2;
                    float p0 = fexp2(acc[mt][nt][hf * 2 + 0] * CE);
                    float p1 = fexp2(acc[mt][nt][hf * 2 + 1] * CE);
                    if (diag && (j0 + col + 0) > growg) p0 = 0.0f;
                    if (diag && (j0 + col + 1) > growg) p1 = 0.0f;
                    *(float2*)&attnp[(size_t)growg * Sc + j0 + col] = make_float2(p0, p1);
                    *(uint32_t*)(sm + APH + rowg * VROWB + col * 2) = pack_hi(p0, p1);
                    *(uint32_t*)(sm + APL + rowg * VROWB + col * 2) = pack_lo(p0, p1);
                    rl += p0 + p1;
                }
                lsum[mt][hf] += rl;
            }
        __syncthreads();

        // PV: ctx += P[128x128] @ V[128x64]   (unnormalized)
#pragma unroll
        for (int ks = 0; ks < 8; ks++) {
            const int k16 = ks * 16;
            uint32_t ph[4][4], pl[4][4];
#pragma unroll
            for (int mt = 0; mt < 4; mt++) {
                uint32_t off = (uint32_t)((warp_m + mt * 16 + arow) * VROWB + (k16 + acol) * 2);
                ldsm4(ph[mt], smb + APH + off);
                ldsm4(pl[mt], smb + APL + off);
            }
            uint32_t vh[2][2], vl[2][2];
            {
                uint32_t off = (uint32_t)((wnp + (bg & 1) * 8 + bw) * VROWB
                                          + (k16 + (bg >> 1) * 8) * 2);
                uint32_t t[4];
                ldsm4(t, smb + AVH + off);
                vh[0][0] = t[0]; vh[0][1] = t[2];
                vh[1][0] = t[1]; vh[1][1] = t[3];
                ldsm4(t, smb + AVL + off);
                vl[0][0] = t[0]; vl[0][1] = t[2];
                vl[1][0] = t[1]; vl[1][1] = t[3];
            }
#pragma unroll
            for (int mt = 0; mt < 4; mt++)
#pragma unroll
                for (int ntp = 0; ntp < 2; ntp++) {
                    mma16816(ctx[mt][ntp], ph[mt], vh[ntp]);
                    mma16816(ctx[mt][ntp], ph[mt], vl[ntp]);
                    mma16816(ctx[mt][ntp], pl[mt], vh[ntp]);
                }
        }
    }

    // ---- reduce row sums l: 4 lanes per row, then 4 warp_n groups via smem
#pragma unroll
    for (int off = 1; off <= 2; off <<= 1)
#pragma unroll
        for (int mt = 0; mt < 4; mt++)
#pragma unroll
            for (int hf = 0; hf < 2; hf++)
                lsum[mt][hf] += __shfl_xor_sync(0xffffffffu, lsum[mt][hf], off);

    __syncthreads();
    float* smR = (float*)(sm + AVH);      // 4*128 partials + 128 finals
    float* smF = smR + 512;
    if ((lane & 3) == 0) {
        const int g = wid >> 1;
#pragma unroll
        for (int mt = 0; mt < 4; mt++)
#pragma unroll
            for (int hf = 0; hf < 2; hf++)
                smR[g * 128 + warp_m + mt * 16 + lr + hf * 8] = lsum[mt][hf];
    }
    __syncthreads();
    if (tid < 128) {
        float l = smR[tid] + smR[128 + tid] + smR[256 + tid] + smR[384 + tid];
        smF[tid] = 1.0f / l;
        g_lbuf[bh * Sc + r0 + tid] = l;
    }
    __syncthreads();

    // ---- write normalized ctx
#pragma unroll
    for (int mt = 0; mt < 4; mt++)
#pragma unroll
        for (int ntp = 0; ntp < 2; ntp++) {
            int dcol = h * DPc + wnp + ntp * 8 + lc2;
#pragma unroll
            for (int hf = 0; hf < 2; hf++) {
                int rowl = warp_m + mt * 16 + lr + hf * 8;
                float inv = smF[rowl];
                int row = r0 + rowl;
                *(float2*)&g_ctx[(size_t)((size_t)b * Sc + row) * Dc + dcol] =
                    make_float2(ctx[mt][ntp][hf * 2 + 0] * inv,
                                ctx[mt][ntp][hf * 2 + 1] * inv);
            }
        }
}

// ---------------------------------------------------------------------------
// Normalize lower-tri attn rows by 1/l and zero-fill the causal upper part.
// ---------------------------------------------------------------------------
__global__ __launch_bounds__(256, 1)
void attn_norm_fill(float* __restrict__ attn)
{
    const int b = blockIdx.z, h = blockIdx.y, it = blockIdx.x;
    const int r0 = it * 128;
    const int tid = threadIdx.x;
    const size_t bh = (size_t)(b * Hc + h);
    float* ap = attn + bh * Sc * Sc;

    __shared__ float inv[128];
    if (tid < 128) inv[tid] = 1.0f / g_lbuf[bh * Sc + r0 + tid];
    __syncthreads();

    const int lim4 = (it + 1) * 32;   // valid float4 columns
    for (int idx = tid; idx < 128 * 512; idx += 256) {
        int row = idx >> 9;
        int c4 = idx & 511;
        float4* p = (float4*)&ap[(size_t)(r0 + row) * Sc + c4 * 4];
        if (c4 < lim4) {
            float s = inv[row];
            float4 vv = *p;
            vv.x *= s; vv.y *= s; vv.z *= s; vv.w *= s;
            *p = vv;
        } else {
            *p = make_float4(0.f, 0.f, 0.f, 0.f);
        }
    }
}

// ---------------------------------------------------------------------------
extern "C" void kernel_launch(void* const* d_in, const int* in_sizes, int n_in,
                              void* d_out, int out_size)
{
    (void)in_sizes; (void)n_in; (void)out_size;
    const float* Q   = (const float*)d_in[0];
    const float* Kin = (const float*)d_in[1];
    const float* Vin = (const float*)d_in[2];
    const float* Wq = (const float*)d_in[4];
    const float* bq = (const float*)d_in[5];
    const float* Wk = (const float*)d_in[6];
    const float* bk = (const float*)d_in[7];
    const float* Wv = (const float*)d_in[8];
    const float* bv = (const float*)d_in[9];
    const float* Wo = (const float*)d_in[10];
    const float* bo = (const float*)d_in[11];

    float* out  = (float*)d_out;
    float* attn = out + SZ_QKV;
    float* qo   = attn + SZ_ATTN;
    float* ko   = qo + SZ_QKV;
    float* vo   = ko + SZ_QKV;

    void* ctxp = nullptr;
    cudaGetSymbolAddress(&ctxp, g_ctx);

    const int gsm = 8 * PLANE;
    cudaFuncSetAttribute(gemm_mma_kernel,
                         cudaFuncAttributeMaxDynamicSharedMemorySize, gsm);
    cudaFuncSetAttribute(gemm_mma_qkv,
                         cudaFuncAttributeMaxDynamicSharedMemorySize, gsm);
    cudaFuncSetAttribute(attn_fused_mma,
                         cudaFuncAttributeMaxDynamicSharedMemorySize, SM2_TOT);

    const int M = Bc * Sc;

    QKVParams qp;
    qp.A[0] = Q;   qp.W[0] = Wq; qp.b[0] = bq; qp.C[0] = qo;
    qp.A[1] = Kin; qp.W[1] = Wk; qp.b[1] = bk; qp.C[1] = ko;
    qp.A[2] = Vin; qp.W[2] = Wv; qp.b[2] = bv; qp.C[2] = vo;

    dim3 qgrid(Dc / 128, M / 128, 3);
    gemm_mma_qkv<<<qgrid, 256, gsm>>>(qp, M, Dc, Dc);

    dim3 agrid(Sc / 128, Hc, Bc);
    attn_fused_mma<<<agrid, 256, SM2_TOT>>>(qo, ko, vo, attn);
    attn_norm_fill<<<agrid, 256>>>(attn);

    dim3 ggrid(Dc / 128, M / 128);
    gemm_mma_kernel<<<ggrid, 256, gsm>>>((const float*)ctxp, Wo, bo, out,
                                         M, Dc, Dc);
}